// round 1
// baseline (speedup 1.0000x reference)
#include <cuda_runtime.h>
#include <math.h>
#include <float.h>

#define DIMM   1024
#define NHEADS 16
#define DH     64
#define SEQ    8192
#define BATCH  2
#define NTOK   (BATCH*SEQ)     // 16384
#define BHTOT  (BATCH*NHEADS)  // 32
#define NWIN   (SEQ/128)       // 64
#define TBLROWS (SEQ + 256)    // rope table rows (need up to n+128)

// ---------------- static device scratch (no allocations allowed) ----------------
__device__ float g_qkv[(size_t)NTOK * 3072];          // 192 MB
__device__ float g_q[(size_t)BHTOT * SEQ * DH];       // 64 MB
__device__ float g_k[(size_t)BHTOT * SEQ * DH];
__device__ float g_v[(size_t)BHTOT * SEQ * DH];
__device__ float g_attn[(size_t)NTOK * DIMM];         // 64 MB
__device__ float g_cos[(size_t)TBLROWS * 32];
__device__ float g_sin[(size_t)TBLROWS * 32];

// ---------------- rope table ----------------
__global__ void rope_table_kernel() {
    int idx = blockIdx.x * 256 + threadIdx.x;
    if (idx >= TBLROWS * 32) return;
    int t = idx >> 5, d = idx & 31;
    // inv_freq[d] = 10000^(-d/32) = exp(-d * ln(10000)/32)
    float invf = expf(-(float)d * (9.210340371976184f / 32.0f));
    float ang = (float)t * invf;
    float s, c;
    sincosf(ang, &s, &c);
    g_cos[idx] = c;
    g_sin[idx] = s;
}

// ---------------- fp32 SGEMM: C[M,N] = A[M,K] @ B[K,N], all row-major ----------
// 128x128 tile, BK=8, 256 threads, 8x8 per-thread microtile.
__global__ void __launch_bounds__(256) sgemm_kernel(
    const float* __restrict__ A, const float* __restrict__ B,
    float* __restrict__ C, int M, int N, int K)
{
    __shared__ float As[8][128];
    __shared__ float Bs[8][128];
    int tid = threadIdx.x;
    int brow = blockIdx.y, bcol = blockIdx.x;
    const float* Ab = A + (size_t)brow * 128 * K;
    const float* Bb = B + (size_t)bcol * 128;

    int a_row = tid >> 1;          // 0..127
    int a_col = (tid & 1) * 4;     // 0 or 4
    int b_row = tid >> 5;          // 0..7
    int b_col = (tid & 31) * 4;    // 0..124
    int tx = tid & 15, ty = tid >> 4;

    float acc[8][8];
    #pragma unroll
    for (int i = 0; i < 8; i++)
        #pragma unroll
        for (int j = 0; j < 8; j++) acc[i][j] = 0.0f;

    for (int k0 = 0; k0 < K; k0 += 8) {
        float4 av = *(const float4*)(Ab + (size_t)a_row * K + k0 + a_col);
        float4 bv = *(const float4*)(Bb + (size_t)(k0 + b_row) * N + b_col);
        __syncthreads();
        As[a_col + 0][a_row] = av.x;
        As[a_col + 1][a_row] = av.y;
        As[a_col + 2][a_row] = av.z;
        As[a_col + 3][a_row] = av.w;
        *(float4*)&Bs[b_row][b_col] = bv;
        __syncthreads();
        #pragma unroll
        for (int kk = 0; kk < 8; kk++) {
            float a_reg[8], b_reg[8];
            *(float4*)&a_reg[0] = *(const float4*)&As[kk][ty * 8];
            *(float4*)&a_reg[4] = *(const float4*)&As[kk][ty * 8 + 4];
            *(float4*)&b_reg[0] = *(const float4*)&Bs[kk][tx * 8];
            *(float4*)&b_reg[4] = *(const float4*)&Bs[kk][tx * 8 + 4];
            #pragma unroll
            for (int i = 0; i < 8; i++)
                #pragma unroll
                for (int j = 0; j < 8; j++)
                    acc[i][j] += a_reg[i] * b_reg[j];
        }
    }
    float* Cb = C + (size_t)(brow * 128 + ty * 8) * N + bcol * 128 + tx * 8;
    #pragma unroll
    for (int i = 0; i < 8; i++) {
        *(float4*)(Cb + (size_t)i * N)     = make_float4(acc[i][0], acc[i][1], acc[i][2], acc[i][3]);
        *(float4*)(Cb + (size_t)i * N + 4) = make_float4(acc[i][4], acc[i][5], acc[i][6], acc[i][7]);
    }
}

// ---------------- normalize + scale + RoPE + split into head-major q/k/v --------
// blockDim (32,8): one warp per (token, head) row.
__global__ void __launch_bounds__(256) norm_rope_split_kernel(
    const float* __restrict__ qkv,
    const float* __restrict__ q_scale,
    const float* __restrict__ k_scale)
{
    int r = blockIdx.x * blockDim.y + threadIdx.y;  // 0 .. NTOK*NHEADS-1
    int lane = threadIdx.x;                         // 0..31 (d and d+32)
    int m = r >> 4;          // global token 0..16383
    int h = r & 15;
    int b = m >> 13;         // /8192
    int nn = m & (SEQ - 1);
    int bh = b * NHEADS + h;

    const float* row = qkv + (size_t)m * 3072 + h * 64;
    float q1 = row[lane],        q2 = row[lane + 32];
    float k1 = row[1024 + lane], k2 = row[1024 + lane + 32];
    float v1 = row[2048 + lane], v2 = row[2048 + lane + 32];

    float qs = q1 * q1 + q2 * q2;
    float ks = k1 * k1 + k2 * k2;
    #pragma unroll
    for (int o = 16; o > 0; o >>= 1) {
        qs += __shfl_xor_sync(0xffffffffu, qs, o);
        ks += __shfl_xor_sync(0xffffffffu, ks, o);
    }
    float qinv = 8.0f / fmaxf(sqrtf(qs), 1e-12f);   // fold SCALE=8 for q
    float kinv = 1.0f / fmaxf(sqrtf(ks), 1e-12f);

    q1 = q1 * qinv * q_scale[lane];  q2 = q2 * qinv * q_scale[lane + 32];
    k1 = k1 * kinv * k_scale[lane];  k2 = k2 * kinv * k_scale[lane + 32];

    // RoPE: q at t = nn + 128, k at t = nn (relative phases match reference)
    int tq = nn + 128, tk = nn;
    float cq = g_cos[tq * 32 + lane], sq = g_sin[tq * 32 + lane];
    float ck = g_cos[tk * 32 + lane], sk = g_sin[tk * 32 + lane];
    float qo1 = q1 * cq - q2 * sq, qo2 = q2 * cq + q1 * sq;
    float ko1 = k1 * ck - k2 * sk, ko2 = k2 * ck + k1 * sk;

    size_t base = ((size_t)bh * SEQ + nn) * 64;
    g_q[base + lane] = qo1;  g_q[base + lane + 32] = qo2;
    g_k[base + lane] = ko1;  g_k[base + lane + 32] = ko2;
    g_v[base + lane] = v1;   g_v[base + lane + 32] = v2;
}

// ---------------- windowed attention (flash-style over 3 look-around chunks) ----
// grid (NWIN, BHTOT), 256 threads. smem: qT[64][128] kT[64][128] vS[128][64] Pt[128][136]
#define ATTN_SMEM_FLOATS (64*128 + 64*128 + 128*64 + 128*136)

__global__ void __launch_bounds__(256) local_attn_kernel() {
    int w  = blockIdx.x;   // window 0..63
    int bh = blockIdx.y;   // 0..31
    extern __shared__ float sm[];
    float* qT = sm;                    // [64][128] d-major
    float* kT = qT + 64 * 128;         // [64][128] d-major
    float* vS = kT + 64 * 128;         // [128][64] j-major
    float* Pt = vS + 128 * 64;         // [128][136] i-major, padded

    int tid = threadIdx.x;
    int tx = tid & 15, ty = tid >> 4;

    const float* qg = g_q + ((size_t)bh * SEQ + (size_t)w * 128) * 64;

    // load q transposed: conflict-free smem stores (consecutive lanes -> consecutive i)
    #pragma unroll
    for (int it = 0; it < 8; it++) {
        int f = tid + it * 256;        // float4 index 0..2047
        int i = f & 127, d4 = (f >> 7) * 4;
        float4 v = *(const float4*)(qg + (size_t)i * 64 + d4);
        qT[(d4 + 0) * 128 + i] = v.x;
        qT[(d4 + 1) * 128 + i] = v.y;
        qT[(d4 + 2) * 128 + i] = v.z;
        qT[(d4 + 3) * 128 + i] = v.w;
    }

    float O[8][4];
    float mrow[8], lrow[8];
    #pragma unroll
    for (int r = 0; r < 8; r++) {
        mrow[r] = -FLT_MAX; lrow[r] = 0.0f;
        #pragma unroll
        for (int c = 0; c < 4; c++) O[r][c] = 0.0f;
    }

    for (int ch = 0; ch < 3; ch++) {
        int kw = w - 1 + ch;
        if (kw < 0 || kw >= NWIN) continue;
        const float* kg = g_k + ((size_t)bh * SEQ + (size_t)kw * 128) * 64;
        const float* vg = g_v + ((size_t)bh * SEQ + (size_t)kw * 128) * 64;

        __syncthreads();  // previous chunk fully consumed kT/vS/Pt
        #pragma unroll
        for (int it = 0; it < 8; it++) {
            int f = tid + it * 256;
            int i = f & 127, d4 = (f >> 7) * 4;
            float4 v = *(const float4*)(kg + (size_t)i * 64 + d4);
            kT[(d4 + 0) * 128 + i] = v.x;
            kT[(d4 + 1) * 128 + i] = v.y;
            kT[(d4 + 2) * 128 + i] = v.z;
            kT[(d4 + 3) * 128 + i] = v.w;
        }
        #pragma unroll
        for (int it = 0; it < 8; it++) {
            int f = tid + it * 256;
            int j = f >> 4, d4 = (f & 15) * 4;
            *(float4*)(vS + j * 64 + d4) = *(const float4*)(vg + (size_t)j * 64 + d4);
        }
        __syncthreads();

        // S = q @ k^T  (rows ty*8.., cols tx*8..)
        float S[8][8];
        #pragma unroll
        for (int r = 0; r < 8; r++)
            #pragma unroll
            for (int c = 0; c < 8; c++) S[r][c] = 0.0f;

        #pragma unroll 16
        for (int d = 0; d < 64; d++) {
            float a[8], bb[8];
            *(float4*)&a[0]  = *(const float4*)(qT + d * 128 + ty * 8);
            *(float4*)&a[4]  = *(const float4*)(qT + d * 128 + ty * 8 + 4);
            *(float4*)&bb[0] = *(const float4*)(kT + d * 128 + tx * 8);
            *(float4*)&bb[4] = *(const float4*)(kT + d * 128 + tx * 8 + 4);
            #pragma unroll
            for (int r = 0; r < 8; r++)
                #pragma unroll
                for (int c = 0; c < 8; c++)
                    S[r][c] += a[r] * bb[c];
        }

        // mask: ch=0 valid iff j>=i ; ch=2 valid iff j<=i
        if (ch == 0) {
            #pragma unroll
            for (int r = 0; r < 8; r++)
                #pragma unroll
                for (int c = 0; c < 8; c++)
                    if (tx * 8 + c < ty * 8 + r) S[r][c] = -FLT_MAX;
        } else if (ch == 2) {
            #pragma unroll
            for (int r = 0; r < 8; r++)
                #pragma unroll
                for (int c = 0; c < 8; c++)
                    if (tx * 8 + c > ty * 8 + r) S[r][c] = -FLT_MAX;
        }

        // online softmax update (reductions across the 16 tx lanes of each half-warp)
        #pragma unroll
        for (int r = 0; r < 8; r++) {
            float rm = S[r][0];
            #pragma unroll
            for (int c = 1; c < 8; c++) rm = fmaxf(rm, S[r][c]);
            #pragma unroll
            for (int o = 1; o < 16; o <<= 1)
                rm = fmaxf(rm, __shfl_xor_sync(0xffffffffu, rm, o));
            float mn = fmaxf(mrow[r], rm);
            float alpha = expf(mrow[r] - mn);   // first chunk: exp(-inf)=0
            float rs = 0.0f;
            #pragma unroll
            for (int c = 0; c < 8; c++) {
                float p = expf(S[r][c] - mn);   // masked -> 0
                S[r][c] = p;
                rs += p;
            }
            #pragma unroll
            for (int o = 1; o < 16; o <<= 1)
                rs += __shfl_xor_sync(0xffffffffu, rs, o);
            lrow[r] = lrow[r] * alpha + rs;
            mrow[r] = mn;
            #pragma unroll
            for (int c = 0; c < 4; c++) O[r][c] *= alpha;
        }

        // write P to smem (float4, conflict-free)
        #pragma unroll
        for (int r = 0; r < 8; r++) {
            float* pr = Pt + (ty * 8 + r) * 136 + tx * 8;
            *(float4*)(pr)     = make_float4(S[r][0], S[r][1], S[r][2], S[r][3]);
            *(float4*)(pr + 4) = make_float4(S[r][4], S[r][5], S[r][6], S[r][7]);
        }
        __syncthreads();

        // O += P @ V   (cols tx*4..tx*4+3)
        #pragma unroll 4
        for (int j0 = 0; j0 < 128; j0 += 4) {
            float4 b0 = *(const float4*)(vS + (j0 + 0) * 64 + tx * 4);
            float4 b1 = *(const float4*)(vS + (j0 + 1) * 64 + tx * 4);
            float4 b2 = *(const float4*)(vS + (j0 + 2) * 64 + tx * 4);
            float4 b3 = *(const float4*)(vS + (j0 + 3) * 64 + tx * 4);
            #pragma unroll
            for (int r = 0; r < 8; r++) {
                float4 a = *(const float4*)(Pt + (ty * 8 + r) * 136 + j0);
                O[r][0] += a.x * b0.x + a.y * b1.x + a.z * b2.x + a.w * b3.x;
                O[r][1] += a.x * b0.y + a.y * b1.y + a.z * b2.y + a.w * b3.y;
                O[r][2] += a.x * b0.z + a.y * b1.z + a.z * b2.z + a.w * b3.z;
                O[r][3] += a.x * b0.w + a.y * b1.w + a.z * b2.w + a.w * b3.w;
            }
        }
    }

    // epilogue: normalize and write to [b, n, h*64+d]
    int b = bh >> 4, h = bh & 15;
    size_t out_base = ((size_t)(b * SEQ + w * 128)) * DIMM + h * 64;
    #pragma unroll
    for (int r = 0; r < 8; r++) {
        float inv = 1.0f / lrow[r];
        int i = ty * 8 + r;
        *(float4*)(g_attn + out_base + (size_t)i * DIMM + tx * 4) =
            make_float4(O[r][0] * inv, O[r][1] * inv, O[r][2] * inv, O[r][3] * inv);
    }
}

// ---------------- launch ----------------
extern "C" void kernel_launch(void* const* d_in, const int* in_sizes, int n_in,
                              void* d_out, int out_size) {
    const float* x       = (const float*)d_in[0];
    const float* w_qkv   = (const float*)d_in[1];
    const float* w_out   = (const float*)d_in[2];
    const float* q_scale = (const float*)d_in[3];
    const float* k_scale = (const float*)d_in[4];
    float* out = (float*)d_out;

    void *p_qkv, *p_attn;
    cudaGetSymbolAddress(&p_qkv, g_qkv);
    cudaGetSymbolAddress(&p_attn, g_attn);

    int attn_smem = ATTN_SMEM_FLOATS * (int)sizeof(float);
    cudaFuncSetAttribute(local_attn_kernel,
                         cudaFuncAttributeMaxDynamicSharedMemorySize, attn_smem);

    // 1) rope tables
    rope_table_kernel<<<(TBLROWS * 32 + 255) / 256, 256>>>();

    // 2) QKV projection: [16384,1024] @ [1024,3072]
    sgemm_kernel<<<dim3(3072 / 128, NTOK / 128), 256>>>(
        x, w_qkv, (float*)p_qkv, NTOK, 3072, DIMM);

    // 3) l2norm + scale + rope + split
    norm_rope_split_kernel<<<(NTOK * NHEADS) / 8, dim3(32, 8)>>>(
        (const float*)p_qkv, q_scale, k_scale);

    // 4) windowed attention
    local_attn_kernel<<<dim3(NWIN, BHTOT), 256, attn_smem>>>();

    // 5) output projection: [16384,1024] @ [1024,1024]
    sgemm_kernel<<<dim3(DIMM / 128, NTOK / 128), 256>>>(
        (const float*)p_attn, w_out, out, NTOK, DIMM, DIMM);
}

// round 4
// speedup vs baseline: 1.9544x; 1.9544x over previous
#include <cuda_runtime.h>
#include <cuda_bf16.h>
#include <stdint.h>
#include <math.h>
#include <float.h>

#define DIMM   1024
#define NHEADS 16
#define DH     64
#define SEQ    8192
#define BATCH  2
#define NTOK   (BATCH*SEQ)     // 16384
#define BHTOT  (BATCH*NHEADS)  // 32
#define NWIN   (SEQ/128)       // 64
#define TBLROWS (SEQ + 256)
#define KTOT   3072            // split K' = 3*1024

// ---------------- static device scratch ----------------
__device__ float g_qkv[(size_t)NTOK * 3072];
__device__ float g_q[(size_t)BHTOT * SEQ * DH];
__device__ float g_k[(size_t)BHTOT * SEQ * DH];
__device__ float g_v[(size_t)BHTOT * SEQ * DH];
__device__ float g_attn[(size_t)NTOK * DIMM];
__device__ float g_cos[(size_t)TBLROWS * 32];
__device__ float g_sin[(size_t)TBLROWS * 32];
__device__ __nv_bfloat16 g_a[(size_t)NTOK * KTOT];     // A' split (x, later attn out)
__device__ __nv_bfloat16 g_b1[(size_t)3072 * KTOT];    // w_qkv'^T split
__device__ __nv_bfloat16 g_b2[(size_t)1024 * KTOT];    // w_out'^T split

// ---------------- rope table ----------------
__global__ void rope_table_kernel() {
    int idx = blockIdx.x * 256 + threadIdx.x;
    if (idx >= TBLROWS * 32) return;
    int t = idx >> 5, d = idx & 31;
    float invf = expf(-(float)d * (9.210340371976184f / 32.0f));
    float s, c;
    sincosf((float)t * invf, &s, &c);
    g_cos[idx] = c;
    g_sin[idx] = s;
}

// ---------------- split-bf16 conversions ----------------
// A side: src [NTOK, 1024] f32 -> dst [NTOK, 3072] bf16 chunks (hi, lo, hi)
__global__ void __launch_bounds__(256) convert_a3_kernel(
    const float* __restrict__ src, __nv_bfloat16* __restrict__ dst)
{
    size_t i = (size_t)blockIdx.x * 256 + threadIdx.x;
    int m = (int)(i >> 10), k = (int)(i & 1023);
    float v = src[i];
    __nv_bfloat16 hi = __float2bfloat16(v);
    __nv_bfloat16 lo = __float2bfloat16(v - __bfloat162float(hi));
    __nv_bfloat16* d = dst + (size_t)m * KTOT;
    d[k] = hi; d[1024 + k] = lo; d[2048 + k] = hi;
}

// B side: src [1024, N] f32 row-major -> dst [N, 3072] bf16 (transposed), chunks (hi, hi, lo)
__global__ void __launch_bounds__(1024) convert_b3_kernel(
    const float* __restrict__ src, __nv_bfloat16* __restrict__ dst, int N)
{
    __shared__ float t[32][33];
    int n0 = blockIdx.x * 32, k0 = blockIdx.y * 32;
    int tx = threadIdx.x, ty = threadIdx.y;
    t[ty][tx] = src[(size_t)(k0 + ty) * N + n0 + tx];
    __syncthreads();
    float v = t[tx][ty];   // src[k0+tx][n0+ty]
    __nv_bfloat16 hi = __float2bfloat16(v);
    __nv_bfloat16 lo = __float2bfloat16(v - __bfloat162float(hi));
    size_t base = (size_t)(n0 + ty) * KTOT + k0 + tx;
    dst[base] = hi; dst[base + 1024] = hi; dst[base + 2048] = lo;
}

// ---------------- HMMA bf16 GEMM: C[M,Ntot] = A'[M,3072] @ B'[Ntot,3072]^T ----
// BM=128, BN=128, BK=32, 256 threads, 8 warps (2 M x 4 N), warp tile 64x32.
// 3-stage cp.async pipeline. Fragments via mma.sync.m16n8k16 (row.col).
#define GEMM_NIT   (KTOT / 32)   // 96
#define ROWU       20            // u32 per smem row (16 data + 4 pad, 16B aligned)
#define STAGEU     (2 * 128 * ROWU)   // A + B per stage in u32
#define GEMM_SMEM  (3 * STAGEU * 4)   // 61440 bytes

__device__ __forceinline__ uint32_t smem_u32g(const void* p) {
    uint32_t a;
    asm("{ .reg .u64 t; cvta.to.shared.u64 t, %1; cvt.u32.u64 %0, t; }" : "=r"(a) : "l"(p));
    return a;
}

__device__ __forceinline__ void hmma16816(float c[4], uint32_t a0, uint32_t a1,
                                          uint32_t a2, uint32_t a3,
                                          uint32_t b0, uint32_t b1) {
    asm volatile(
        "mma.sync.aligned.m16n8k16.row.col.f32.bf16.bf16.f32 "
        "{%0,%1,%2,%3}, {%4,%5,%6,%7}, {%8,%9}, {%0,%1,%2,%3};\n"
        : "+f"(c[0]), "+f"(c[1]), "+f"(c[2]), "+f"(c[3])
        : "r"(a0), "r"(a1), "r"(a2), "r"(a3), "r"(b0), "r"(b1));
}

__global__ void __launch_bounds__(256, 2) gemm3x_kernel(
    const __nv_bfloat16* __restrict__ A, const __nv_bfloat16* __restrict__ Bm,
    float* __restrict__ C, int Ntot)
{
    extern __shared__ uint32_t smem[];
    int tid = threadIdx.x;
    int wid = tid >> 5, lane = tid & 31;
    int wm = wid >> 2, wn = wid & 3;       // warp grid 2 x 4
    int g = lane >> 2, tig = lane & 3;
    int brow = blockIdx.y, bcol = blockIdx.x;

    const __nv_bfloat16* Ag = A + (size_t)(brow * 128) * KTOT;
    const __nv_bfloat16* Bg = Bm + (size_t)(bcol * 128) * KTOT;

    uint32_t smb = smem_u32g(smem);

    // cp.async: 512 16B-chunks per tile; thread t does chunks t, t+256.
    int ch0 = tid, ch1 = tid + 256;
    int r0c = ch0 >> 2, c40 = ch0 & 3;     // row, 16B-group
    int r1c = ch1 >> 2, c41 = ch1 & 3;

#define LOAD_STAGE(kc, stg) do { \
    uint32_t ab = smb + (stg) * STAGEU * 4; \
    uint32_t bb = ab + 128 * ROWU * 4; \
    const __nv_bfloat16* gA0 = Ag + (size_t)r0c * KTOT + (kc) * 32 + c40 * 8; \
    const __nv_bfloat16* gA1 = Ag + (size_t)r1c * KTOT + (kc) * 32 + c41 * 8; \
    const __nv_bfloat16* gB0 = Bg + (size_t)r0c * KTOT + (kc) * 32 + c40 * 8; \
    const __nv_bfloat16* gB1 = Bg + (size_t)r1c * KTOT + (kc) * 32 + c41 * 8; \
    asm volatile("cp.async.cg.shared.global [%0], [%1], 16;" :: "r"(ab + (r0c * ROWU + c40 * 4) * 4), "l"(gA0)); \
    asm volatile("cp.async.cg.shared.global [%0], [%1], 16;" :: "r"(ab + (r1c * ROWU + c41 * 4) * 4), "l"(gA1)); \
    asm volatile("cp.async.cg.shared.global [%0], [%1], 16;" :: "r"(bb + (r0c * ROWU + c40 * 4) * 4), "l"(gB0)); \
    asm volatile("cp.async.cg.shared.global [%0], [%1], 16;" :: "r"(bb + (r1c * ROWU + c41 * 4) * 4), "l"(gB1)); \
} while (0)

    LOAD_STAGE(0, 0);
    asm volatile("cp.async.commit_group;" ::: "memory");
    LOAD_STAGE(1, 1);
    asm volatile("cp.async.commit_group;" ::: "memory");
    LOAD_STAGE(2, 2);
    asm volatile("cp.async.commit_group;" ::: "memory");

    float acc[4][4][4];
    #pragma unroll
    for (int mt = 0; mt < 4; mt++)
        #pragma unroll
        for (int nt = 0; nt < 4; nt++)
            #pragma unroll
            for (int e = 0; e < 4; e++) acc[mt][nt][e] = 0.0f;

    for (int kc = 0; kc < GEMM_NIT; kc++) {
        int stg = kc % 3;
        asm volatile("cp.async.wait_group 2;" ::: "memory");
        __syncthreads();

        const uint32_t* As = smem + stg * STAGEU;
        const uint32_t* Bs = As + 128 * ROWU;

        #pragma unroll
        for (int ks = 0; ks < 2; ks++) {
            uint32_t af[4][4], bf[4][2];
            #pragma unroll
            for (int mt = 0; mt < 4; mt++) {
                int r = wm * 64 + mt * 16 + g;
                af[mt][0] = As[r * ROWU + ks * 8 + tig];
                af[mt][1] = As[(r + 8) * ROWU + ks * 8 + tig];
                af[mt][2] = As[r * ROWU + ks * 8 + tig + 4];
                af[mt][3] = As[(r + 8) * ROWU + ks * 8 + tig + 4];
            }
            #pragma unroll
            for (int nt = 0; nt < 4; nt++) {
                int n = wn * 32 + nt * 8 + g;
                bf[nt][0] = Bs[n * ROWU + ks * 8 + tig];
                bf[nt][1] = Bs[n * ROWU + ks * 8 + tig + 4];
            }
            #pragma unroll
            for (int mt = 0; mt < 4; mt++)
                #pragma unroll
                for (int nt = 0; nt < 4; nt++)
                    hmma16816(acc[mt][nt], af[mt][0], af[mt][1], af[mt][2], af[mt][3],
                              bf[nt][0], bf[nt][1]);
        }
        __syncthreads();
        if (kc + 3 < GEMM_NIT) LOAD_STAGE(kc + 3, stg);
        asm volatile("cp.async.commit_group;" ::: "memory");   // empty group when no load
    }

    // epilogue
    #pragma unroll
    for (int mt = 0; mt < 4; mt++) {
        int row = brow * 128 + wm * 64 + mt * 16 + g;
        #pragma unroll
        for (int nt = 0; nt < 4; nt++) {
            int col = bcol * 128 + wn * 32 + nt * 8 + tig * 2;
            *(float2*)(C + (size_t)row * Ntot + col) =
                make_float2(acc[mt][nt][0], acc[mt][nt][1]);
            *(float2*)(C + (size_t)(row + 8) * Ntot + col) =
                make_float2(acc[mt][nt][2], acc[mt][nt][3]);
        }
    }
#undef LOAD_STAGE
}

// ---------------- normalize + scale + RoPE + split ----------------
__global__ void __launch_bounds__(256) norm_rope_split_kernel(
    const float* __restrict__ qkv,
    const float* __restrict__ q_scale,
    const float* __restrict__ k_scale)
{
    int r = blockIdx.x * blockDim.y + threadIdx.y;
    int lane = threadIdx.x;
    int m = r >> 4;
    int h = r & 15;
    int b = m >> 13;
    int nn = m & (SEQ - 1);
    int bh = b * NHEADS + h;

    const float* row = qkv + (size_t)m * 3072 + h * 64;
    float q1 = row[lane],        q2 = row[lane + 32];
    float k1 = row[1024 + lane], k2 = row[1024 + lane + 32];
    float v1 = row[2048 + lane], v2 = row[2048 + lane + 32];

    float qs = q1 * q1 + q2 * q2;
    float ks = k1 * k1 + k2 * k2;
    #pragma unroll
    for (int o = 16; o > 0; o >>= 1) {
        qs += __shfl_xor_sync(0xffffffffu, qs, o);
        ks += __shfl_xor_sync(0xffffffffu, ks, o);
    }
    float qinv = 8.0f / fmaxf(sqrtf(qs), 1e-12f);
    float kinv = 1.0f / fmaxf(sqrtf(ks), 1e-12f);

    q1 = q1 * qinv * q_scale[lane];  q2 = q2 * qinv * q_scale[lane + 32];
    k1 = k1 * kinv * k_scale[lane];  k2 = k2 * kinv * k_scale[lane + 32];

    int tq = nn + 128, tk = nn;
    float cq = g_cos[tq * 32 + lane], sq = g_sin[tq * 32 + lane];
    float ck = g_cos[tk * 32 + lane], sk = g_sin[tk * 32 + lane];
    float qo1 = q1 * cq - q2 * sq, qo2 = q2 * cq + q1 * sq;
    float ko1 = k1 * ck - k2 * sk, ko2 = k2 * ck + k1 * sk;

    size_t base = ((size_t)bh * SEQ + nn) * 64;
    g_q[base + lane] = qo1;  g_q[base + lane + 32] = qo2;
    g_k[base + lane] = ko1;  g_k[base + lane + 32] = ko2;
    g_v[base + lane] = v1;   g_v[base + lane + 32] = v2;
}

// ---------------- windowed attention ----------------
#define ATTN_SMEM_FLOATS (64*128 + 64*128 + 128*64 + 128*136)

__global__ void __launch_bounds__(256) local_attn_kernel() {
    int w  = blockIdx.x;
    int bh = blockIdx.y;
    extern __shared__ float smf[];
    float* qT = smf;
    float* kT = qT + 64 * 128;
    float* vS = kT + 64 * 128;
    float* Pt = vS + 128 * 64;

    int tid = threadIdx.x;
    int tx = tid & 15, ty = tid >> 4;

    const float* qg = g_q + ((size_t)bh * SEQ + (size_t)w * 128) * 64;

    #pragma unroll
    for (int it = 0; it < 8; it++) {
        int f = tid + it * 256;
        int i = f & 127, d4 = (f >> 7) * 4;
        float4 v = *(const float4*)(qg + (size_t)i * 64 + d4);
        qT[(d4 + 0) * 128 + i] = v.x;
        qT[(d4 + 1) * 128 + i] = v.y;
        qT[(d4 + 2) * 128 + i] = v.z;
        qT[(d4 + 3) * 128 + i] = v.w;
    }

    float O[8][4];
    float mrow[8], lrow[8];
    #pragma unroll
    for (int r = 0; r < 8; r++) {
        mrow[r] = -FLT_MAX; lrow[r] = 0.0f;
        #pragma unroll
        for (int c = 0; c < 4; c++) O[r][c] = 0.0f;
    }

    for (int ch = 0; ch < 3; ch++) {
        int kw = w - 1 + ch;
        if (kw < 0 || kw >= NWIN) continue;
        const float* kg = g_k + ((size_t)bh * SEQ + (size_t)kw * 128) * 64;
        const float* vg = g_v + ((size_t)bh * SEQ + (size_t)kw * 128) * 64;

        __syncthreads();
        #pragma unroll
        for (int it = 0; it < 8; it++) {
            int f = tid + it * 256;
            int i = f & 127, d4 = (f >> 7) * 4;
            float4 v = *(const float4*)(kg + (size_t)i * 64 + d4);
            kT[(d4 + 0) * 128 + i] = v.x;
            kT[(d4 + 1) * 128 + i] = v.y;
            kT[(d4 + 2) * 128 + i] = v.z;
            kT[(d4 + 3) * 128 + i] = v.w;
        }
        #pragma unroll
        for (int it = 0; it < 8; it++) {
            int f = tid + it * 256;
            int j = f >> 4, d4 = (f & 15) * 4;
            *(float4*)(vS + j * 64 + d4) = *(const float4*)(vg + (size_t)j * 64 + d4);
        }
        __syncthreads();

        float S[8][8];
        #pragma unroll
        for (int r = 0; r < 8; r++)
            #pragma unroll
            for (int c = 0; c < 8; c++) S[r][c] = 0.0f;

        #pragma unroll 16
        for (int d = 0; d < 64; d++) {
            float a[8], bb[8];
            *(float4*)&a[0]  = *(const float4*)(qT + d * 128 + ty * 8);
            *(float4*)&a[4]  = *(const float4*)(qT + d * 128 + ty * 8 + 4);
            *(float4*)&bb[0] = *(const float4*)(kT + d * 128 + tx * 8);
            *(float4*)&bb[4] = *(const float4*)(kT + d * 128 + tx * 8 + 4);
            #pragma unroll
            for (int r = 0; r < 8; r++)
                #pragma unroll
                for (int c = 0; c < 8; c++)
                    S[r][c] += a[r] * bb[c];
        }

        if (ch == 0) {
            #pragma unroll
            for (int r = 0; r < 8; r++)
                #pragma unroll
                for (int c = 0; c < 8; c++)
                    if (tx * 8 + c < ty * 8 + r) S[r][c] = -FLT_MAX;
        } else if (ch == 2) {
            #pragma unroll
            for (int r = 0; r < 8; r++)
                #pragma unroll
                for (int c = 0; c < 8; c++)
                    if (tx * 8 + c > ty * 8 + r) S[r][c] = -FLT_MAX;
        }

        #pragma unroll
        for (int r = 0; r < 8; r++) {
            float rm = S[r][0];
            #pragma unroll
            for (int c = 1; c < 8; c++) rm = fmaxf(rm, S[r][c]);
            #pragma unroll
            for (int o = 1; o < 16; o <<= 1)
                rm = fmaxf(rm, __shfl_xor_sync(0xffffffffu, rm, o));
            float mn = fmaxf(mrow[r], rm);
            float alpha = expf(mrow[r] - mn);
            float rs = 0.0f;
            #pragma unroll
            for (int c = 0; c < 8; c++) {
                float p = expf(S[r][c] - mn);
                S[r][c] = p;
                rs += p;
            }
            #pragma unroll
            for (int o = 1; o < 16; o <<= 1)
                rs += __shfl_xor_sync(0xffffffffu, rs, o);
            lrow[r] = lrow[r] * alpha + rs;
            mrow[r] = mn;
            #pragma unroll
            for (int c = 0; c < 4; c++) O[r][c] *= alpha;
        }

        #pragma unroll
        for (int r = 0; r < 8; r++) {
            float* pr = Pt + (ty * 8 + r) * 136 + tx * 8;
            *(float4*)(pr)     = make_float4(S[r][0], S[r][1], S[r][2], S[r][3]);
            *(float4*)(pr + 4) = make_float4(S[r][4], S[r][5], S[r][6], S[r][7]);
        }
        __syncthreads();

        #pragma unroll 4
        for (int j0 = 0; j0 < 128; j0 += 4) {
            float4 b0 = *(const float4*)(vS + (j0 + 0) * 64 + tx * 4);
            float4 b1 = *(const float4*)(vS + (j0 + 1) * 64 + tx * 4);
            float4 b2 = *(const float4*)(vS + (j0 + 2) * 64 + tx * 4);
            float4 b3 = *(const float4*)(vS + (j0 + 3) * 64 + tx * 4);
            #pragma unroll
            for (int r = 0; r < 8; r++) {
                float4 a = *(const float4*)(Pt + (ty * 8 + r) * 136 + j0);
                O[r][0] += a.x * b0.x + a.y * b1.x + a.z * b2.x + a.w * b3.x;
                O[r][1] += a.x * b0.y + a.y * b1.y + a.z * b2.y + a.w * b3.y;
                O[r][2] += a.x * b0.z + a.y * b1.z + a.z * b2.z + a.w * b3.z;
                O[r][3] += a.x * b0.w + a.y * b1.w + a.z * b2.w + a.w * b3.w;
            }
        }
    }

    int b = bh >> 4, h = bh & 15;
    size_t out_base = ((size_t)(b * SEQ + w * 128)) * DIMM + h * 64;
    #pragma unroll
    for (int r = 0; r < 8; r++) {
        float inv = 1.0f / lrow[r];
        int i = ty * 8 + r;
        *(float4*)(g_attn + out_base + (size_t)i * DIMM + tx * 4) =
            make_float4(O[r][0] * inv, O[r][1] * inv, O[r][2] * inv, O[r][3] * inv);
    }
}

// ---------------- launch ----------------
extern "C" void kernel_launch(void* const* d_in, const int* in_sizes, int n_in,
                              void* d_out, int out_size) {
    const float* x       = (const float*)d_in[0];
    const float* w_qkv   = (const float*)d_in[1];
    const float* w_out   = (const float*)d_in[2];
    const float* q_scale = (const float*)d_in[3];
    const float* k_scale = (const float*)d_in[4];
    float* out = (float*)d_out;

    void *p_qkv, *p_attn, *p_a, *p_b1, *p_b2;
    cudaGetSymbolAddress(&p_qkv, g_qkv);
    cudaGetSymbolAddress(&p_attn, g_attn);
    cudaGetSymbolAddress(&p_a, g_a);
    cudaGetSymbolAddress(&p_b1, g_b1);
    cudaGetSymbolAddress(&p_b2, g_b2);

    int attn_smem = ATTN_SMEM_FLOATS * (int)sizeof(float);
    cudaFuncSetAttribute(local_attn_kernel,
                         cudaFuncAttributeMaxDynamicSharedMemorySize, attn_smem);
    cudaFuncSetAttribute(gemm3x_kernel,
                         cudaFuncAttributeMaxDynamicSharedMemorySize, GEMM_SMEM);

    // 1) rope tables
    rope_table_kernel<<<(TBLROWS * 32 + 255) / 256, 256>>>();

    // 2) split-bf16 conversions
    convert_a3_kernel<<<(NTOK * 1024) / 256, 256>>>(x, (__nv_bfloat16*)p_a);
    convert_b3_kernel<<<dim3(3072 / 32, 1024 / 32), dim3(32, 32)>>>(
        w_qkv, (__nv_bfloat16*)p_b1, 3072);
    convert_b3_kernel<<<dim3(1024 / 32, 1024 / 32), dim3(32, 32)>>>(
        w_out, (__nv_bfloat16*)p_b2, 1024);

    // 3) QKV projection (HMMA): [16384,3072] = A' @ B1'^T
    gemm3x_kernel<<<dim3(3072 / 128, NTOK / 128), 256, GEMM_SMEM>>>(
        (const __nv_bfloat16*)p_a, (const __nv_bfloat16*)p_b1, (float*)p_qkv, 3072);

    // 4) l2norm + scale + rope + split
    norm_rope_split_kernel<<<(NTOK * NHEADS) / 8, dim3(32, 8)>>>(
        (const float*)p_qkv, q_scale, k_scale);

    // 5) windowed attention
    local_attn_kernel<<<dim3(NWIN, BHTOT), 256, attn_smem>>>();

    // 6) convert attention output, then output projection
    convert_a3_kernel<<<(NTOK * 1024) / 256, 256>>>(
        (const float*)p_attn, (__nv_bfloat16*)p_a);
    gemm3x_kernel<<<dim3(1024 / 128, NTOK / 128), 256, GEMM_SMEM>>>(
        (const __nv_bfloat16*)p_a, (const __nv_bfloat16*)p_b2, out, 1024);
}